// round 2
// baseline (speedup 1.0000x reference)
#include <cuda_runtime.h>

// CTC loss forward. Per-state extended-range floats: alpha[s] = v * 2^e,
// v in [1,2) (fp32), e int32. One warp per batch; 5 states/thread (L=129<=160).
// Exponent alignment is exact (power-of-2 scales built by bit ops), so there is
// no global-underflow failure mode; per-state window is the full fp32 range
// relative to each state's own magnitude (~87 nats), matching log-domain fp32.

#define NST 5
#define PF 8
#define EMIN (-(1 << 27))

__device__ float g_loss[1024];

__global__ void __launch_bounds__(32, 1)
ctc_alpha_kernel(const float* __restrict__ logp,
                 const int* __restrict__ targets,
                 const int* __restrict__ in_len,
                 const int* __restrict__ tgt_len,
                 int T, int B, int C, int S)
{
    const int b    = blockIdx.x;
    const int lane = threadIdx.x;
    const int L    = 2 * S + 1;
    const int* tgt = targets + (size_t)b * S;

    // per-thread constants: class index per state, skip mask per state
    int l[NST];
    int skm[NST];   // all-ones if skip allowed, else 0
#pragma unroll
    for (int j = 0; j < NST; ++j) {
        int s = lane * NST + j;
        bool valid = (s < L);
        int lab = 0;
        if (valid && (s & 1)) lab = tgt[s >> 1];
        l[j] = lab;
        bool skf = false;
        if (valid && s >= 3 && (s & 1)) {
            int lm2 = tgt[(s - 2) >> 1];
            skf = (lab != 0) && (lab != lm2);
        }
        skm[j] = skf ? ~0 : 0;
    }

    const size_t BC   = (size_t)B * C;
    const float* base = logp + (size_t)b * C;

    // init t=0
    float v[NST];
    int   e[NST];
#pragma unroll
    for (int j = 0; j < NST; ++j) { v[j] = 1.0f; e[j] = EMIN; }
    if (lane == 0) {
        float y0 = __ldg(base + 0) * 1.4426950408889634f;
        float f0 = floorf(y0);
        e[0] = (int)f0; v[0] = exp2f(y0 - f0);
        if (L > 1) {
            float y1 = __ldg(base + l[1]) * 1.4426950408889634f;
            float f1 = floorf(y1);
            e[1] = (int)f1; v[1] = exp2f(y1 - f1);
        }
    }

    int len = in_len[b];
    if (len > T) len = T;
    if (len < 1) len = 1;

    const float* rowEnd = base + (size_t)(len - 1) * BC;

    // register-pipelined emission log-probs, PF steps ahead
    float lpb[PF][NST];
#pragma unroll
    for (int k = 0; k < PF; ++k) {
        const float* r = base + (size_t)(1 + k) * BC;
        if (r > rowEnd) r = rowEnd;
#pragma unroll
        for (int j = 0; j < NST; ++j) lpb[k][j] = __ldg(r + l[j]);
    }
    const float* rowp = base + (size_t)(1 + PF) * BC;
    if (rowp > rowEnd) rowp = rowEnd;

    int t = 1;
    while (t < len) {
#pragma unroll
        for (int k = 0; k < PF; ++k) {
            if (t < len) {
                // emission probs (off critical path; lp in [-~16, 0])
                float p[NST];
#pragma unroll
                for (int j = 0; j < NST; ++j) p[j] = __expf(lpb[k][j]);

                // neighbors from previous lane (old values)
                float vm1 = __shfl_up_sync(0xffffffffu, v[NST - 1], 1);
                int   em1 = __shfl_up_sync(0xffffffffu, e[NST - 1], 1);
                float vm2 = __shfl_up_sync(0xffffffffu, v[NST - 2], 1);
                int   em2 = __shfl_up_sync(0xffffffffu, e[NST - 2], 1);
                if (lane == 0) { em1 = EMIN; em2 = EMIN; }

                float nv[NST];
                int   ne[NST];
#pragma unroll
                for (int j = 0; j < NST; ++j) {
                    float vb_ = (j == 0) ? vm1 : v[j - 1];
                    int   eb_ = (j == 0) ? em1 : e[j - 1];
                    float vc_ = (j == 0) ? vm2 : (j == 1) ? vm1 : v[j - 2];
                    int   ec_ = (j == 0) ? em2 : (j == 1) ? em1 : e[j - 2];
                    // mask out the skip term (single LOP3)
                    int ecx = (ec_ & skm[j]) | (EMIN & ~skm[j]);
                    int m  = max(e[j], max(eb_, ecx));
                    int da = max(e[j] - m, -126);
                    int db = max(eb_  - m, -126);
                    int dc = max(ecx  - m, -126);
                    float sa = __int_as_float((da + 127) << 23);
                    float sb = __int_as_float((db + 127) << 23);
                    float sc = __int_as_float((dc + 127) << 23);
                    float f  = fmaf(vc_, sc, fmaf(vb_, sb, v[j] * sa));
                    f *= p[j];
                    int bits = __float_as_int(f);
                    ne[j] = m + ((bits >> 23) - 127);
                    nv[j] = __int_as_float((bits & 0x007FFFFF) | 0x3F800000);
                }
#pragma unroll
                for (int j = 0; j < NST; ++j) { v[j] = nv[j]; e[j] = ne[j]; }

                // refill slot k for step t+PF (clamped; unused rows harmless)
#pragma unroll
                for (int j = 0; j < NST; ++j) lpb[k][j] = __ldg(rowp + l[j]);
                rowp += BC;
                if (rowp > rowEnd) rowp = rowEnd;
                ++t;
            }
        }
    }

    // finish: ll = log(alpha[hi] + alpha[hi-1])
    __shared__ float sv[NST * 32];
    __shared__ int   se[NST * 32];
#pragma unroll
    for (int j = 0; j < NST; ++j) {
        sv[lane * NST + j] = v[j];
        se[lane * NST + j] = e[j];
    }
    __syncwarp();
    if (lane == 0) {
        int tl = tgt_len[b];
        int hi = 2 * tl;
        if (hi > L - 1) hi = L - 1;
        float loss = 0.0f;
        if (tl > 0) {
            int   e1_ = se[hi];
            float v1_ = sv[hi];
            int   e2_ = (hi >= 1) ? se[hi - 1] : EMIN;
            float v2_ = (hi >= 1) ? sv[hi - 1] : 1.0f;
            int m = max(e1_, e2_);
            if (m > EMIN / 2) {
                float s1 = v1_ * __int_as_float((max(e1_ - m, -126) + 127) << 23);
                float s2 = v2_ * __int_as_float((max(e2_ - m, -126) + 127) << 23);
                double ll = ((double)m + (double)log2f(s1 + s2)) * 0.69314718055994530942;
                loss = (float)(-ll / (double)tl);
            }
        }
        g_loss[b] = loss;
    }
}

__global__ void ctc_reduce_kernel(float* __restrict__ out, int B)
{
    __shared__ float sh[256];
    float s = 0.0f;
    for (int i = threadIdx.x; i < B; i += blockDim.x) s += g_loss[i];
    sh[threadIdx.x] = s;
    __syncthreads();
    for (int st = 128; st > 0; st >>= 1) {
        if (threadIdx.x < st) sh[threadIdx.x] += sh[threadIdx.x + st];
        __syncthreads();
    }
    if (threadIdx.x == 0) out[0] = sh[0] / (float)B;
}

extern "C" void kernel_launch(void* const* d_in, const int* in_sizes, int n_in,
                              void* d_out, int out_size)
{
    const float* logp    = (const float*)d_in[0];
    const int*   targets = (const int*)d_in[1];
    const int*   in_len  = (const int*)d_in[2];
    const int*   tgt_len = (const int*)d_in[3];

    int B = in_sizes[2];                                   // 128
    int S = in_sizes[1] / B;                               // 64
    int C = 256;
    int T = (int)((size_t)in_sizes[0] / ((size_t)B * C));  // 1024

    ctc_alpha_kernel<<<B, 32>>>(logp, targets, in_len, tgt_len, T, B, C, S);
    ctc_reduce_kernel<<<1, 256>>>((float*)d_out, B);
}